// round 2
// baseline (speedup 1.0000x reference)
#include <cuda_runtime.h>
#include <math.h>

// ---------------------------------------------------------------------------
// FramePriorNetwork: 6-layer transformer (windowed rel-pos attention + conv FFN)
// Fixed shapes from setup_inputs.
// ---------------------------------------------------------------------------
#define B_   4
#define T_   800
#define H_   512
#define FF_  2048
#define NH_  8
#define NL_  6
#define HEAD_ 64
#define BHT_ (B_ * H_ * T_)

// Scratch (device globals: allocation-free rule)
__device__ float g_h[BHT_];
__device__ float g_q[BHT_];
__device__ float g_k[BHT_];
__device__ float g_v[BHT_];
__device__ float g_att[BHT_];
__device__ float g_y[BHT_];
__device__ float g_p[(size_t)B_ * NH_ * T_ * T_];      // scores / probs, ~82 MB
__device__ float g_rl[B_ * NH_ * T_ * 9];              // banded rel-k logits
__device__ float g_ff[B_ * FF_ * T_];                  // FFN hidden / final prior

// ---------------------------------------------------------------------------
// h = x * mask
__global__ void init_h_kernel(const float* __restrict__ x, const float* __restrict__ xm) {
    int idx = blockIdx.x * blockDim.x + threadIdx.x;
    if (idx >= BHT_) return;
    int t = idx % T_;
    int b = idx / (H_ * T_);
    g_h[idx] = x[idx] * xm[b * T_ + t];
}

__global__ void maskh_kernel(const float* __restrict__ xm) {
    int idx = blockIdx.x * blockDim.x + threadIdx.x;
    if (idx >= BHT_) return;
    int t = idx % T_;
    int b = idx / (H_ * T_);
    g_h[idx] *= xm[b * T_ + t];
}

// ---------------------------------------------------------------------------
// Y[b,m,t] = sum_c W[m,c] X[b,c,t] + bias[m]
// 128(M) x 64(t) tile, 256 threads, 8x4 microtile. M must be multiple of 128.
__global__ __launch_bounds__(256) void gemm_kernel(
    const float* __restrict__ W, const float* __restrict__ bias,
    const float* __restrict__ X, float* __restrict__ Y, int M, int K)
{
    __shared__ float Ws[16][128];
    __shared__ float Xs[16][64];
    const int b  = blockIdx.z;
    const int t0 = blockIdx.x * 64;
    const int m0 = blockIdx.y * 128;
    const float* Xb = X + (size_t)b * K * T_;
    float* Yb = Y + (size_t)b * M * T_;
    const int tid = threadIdx.x;
    const int tx = tid & 15, ty = tid >> 4;
    float acc[8][4] = {};
    for (int k0 = 0; k0 < K; k0 += 16) {
        {   // Ws: consecutive tid -> consecutive k (coalesced)
            int kcol = tid & 15, mrow = tid >> 4;
#pragma unroll
            for (int r = 0; r < 8; r++) {
                int m = mrow + r * 16;
                Ws[kcol][m] = W[(size_t)(m0 + m) * K + (k0 + kcol)];
            }
        }
        {
            int col = tid & 63, rq = tid >> 6;
#pragma unroll
            for (int r = 0; r < 4; r++) {
                int kk = r * 4 + rq;
                int t = t0 + col;
                Xs[kk][col] = (t < T_) ? Xb[(size_t)(k0 + kk) * T_ + t] : 0.f;
            }
        }
        __syncthreads();
#pragma unroll
        for (int kk = 0; kk < 16; kk++) {
            float a[8], xv[4];
#pragma unroll
            for (int i = 0; i < 8; i++) a[i] = Ws[kk][ty * 8 + i];
#pragma unroll
            for (int j = 0; j < 4; j++) xv[j] = Xs[kk][tx * 4 + j];
#pragma unroll
            for (int i = 0; i < 8; i++)
#pragma unroll
                for (int j = 0; j < 4; j++) acc[i][j] += a[i] * xv[j];
        }
        __syncthreads();
    }
#pragma unroll
    for (int i = 0; i < 8; i++) {
        int m = m0 + ty * 8 + i;
        float bb = bias[m];
#pragma unroll
        for (int j = 0; j < 4; j++) {
            int t = t0 + tx * 4 + j;
            if (t < T_) Yb[(size_t)m * T_ + t] = acc[i][j] + bb;
        }
    }
}

// ---------------------------------------------------------------------------
// S[bh,t,s] = scale * sum_d Q[bh,d,t] K[bh,d,s]   (64x64 tile, k-depth 64)
__global__ __launch_bounds__(256) void scores_kernel(float scale) {
    __shared__ float Qs[16][64];
    __shared__ float Ks[16][64];
    const int bh = blockIdx.z;
    const int s0 = blockIdx.x * 64;
    const int t0 = blockIdx.y * 64;
    const float* Qb = g_q + (size_t)bh * HEAD_ * T_;
    const float* Kb = g_k + (size_t)bh * HEAD_ * T_;
    float* Sb = g_p + (size_t)bh * T_ * T_;
    const int tid = threadIdx.x;
    const int tx = tid & 15, ty = tid >> 4;
    float acc[4][4] = {};
    for (int k0 = 0; k0 < HEAD_; k0 += 16) {
        int col = tid & 63, rq = tid >> 6;
#pragma unroll
        for (int r = 0; r < 4; r++) {
            int kk = r * 4 + rq;
            int t = t0 + col;
            Qs[kk][col] = (t < T_) ? Qb[(size_t)(k0 + kk) * T_ + t] : 0.f;
            int s = s0 + col;
            Ks[kk][col] = (s < T_) ? Kb[(size_t)(k0 + kk) * T_ + s] : 0.f;
        }
        __syncthreads();
#pragma unroll
        for (int kk = 0; kk < 16; kk++) {
            float a[4], xv[4];
#pragma unroll
            for (int i = 0; i < 4; i++) a[i] = Qs[kk][ty * 4 + i];
#pragma unroll
            for (int j = 0; j < 4; j++) xv[j] = Ks[kk][tx * 4 + j];
#pragma unroll
            for (int i = 0; i < 4; i++)
#pragma unroll
                for (int j = 0; j < 4; j++) acc[i][j] += a[i] * xv[j];
        }
        __syncthreads();
    }
#pragma unroll
    for (int i = 0; i < 4; i++) {
        int t = t0 + ty * 4 + i;
        if (t >= T_) continue;
#pragma unroll
        for (int j = 0; j < 4; j++) {
            int s = s0 + tx * 4 + j;
            if (s < T_) Sb[(size_t)t * T_ + s] = acc[i][j] * scale;
        }
    }
}

// ---------------------------------------------------------------------------
// rl[bh,t,j] = scale * sum_d Q[bh,d,t] * ek[j,d],  j = 0..8 (rel disp -4..+4)
__global__ void relk_kernel(const float* __restrict__ ek, float scale) {
    int w = (blockIdx.x * blockDim.x + threadIdx.x) >> 5;
    int lane = threadIdx.x & 31;
    if (w >= B_ * NH_ * T_) return;
    int bh = w / T_, t = w % T_;
    const float* qb = g_q + (size_t)bh * HEAD_ * T_ + t;
    float q0 = qb[(size_t)lane * T_] * scale;
    float q1 = qb[(size_t)(lane + 32) * T_] * scale;
#pragma unroll
    for (int j = 0; j < 9; j++) {
        float v = q0 * ek[j * HEAD_ + lane] + q1 * ek[j * HEAD_ + lane + 32];
#pragma unroll
        for (int off = 16; off > 0; off >>= 1) v += __shfl_down_sync(0xffffffffu, v, off);
        if (lane == 0) g_rl[w * 9 + j] = v;
    }
}

// ---------------------------------------------------------------------------
// Row softmax with banded rel bias and masking. One block per (bh, t) row.
__global__ __launch_bounds__(256) void softmax_kernel(const float* __restrict__ xm) {
    const int row = blockIdx.x;
    const int bh = row / T_, t = row % T_;
    const int b = bh / NH_;
    float* P = g_p + (size_t)bh * T_ * T_ + (size_t)t * T_;
    const float* rl = g_rl + (size_t)row * 9;
    const float mt = xm[b * T_ + t];
    const int tid = threadIdx.x;
    float v[4];
#pragma unroll
    for (int r = 0; r < 4; r++) {
        int s = tid + r * 256;
        float val = -1e30f;
        if (s < T_) {
            val = P[s];
            int j = s - t + 4;
            if (j >= 0 && j < 9) val += rl[j];
            if (mt == 0.f || xm[b * T_ + s] == 0.f) val = -10000.0f;
        }
        v[r] = val;
    }
    __shared__ float red[256];
    float mx = fmaxf(fmaxf(v[0], v[1]), fmaxf(v[2], v[3]));
    red[tid] = mx;
    __syncthreads();
    for (int off = 128; off > 0; off >>= 1) {
        if (tid < off) red[tid] = fmaxf(red[tid], red[tid + off]);
        __syncthreads();
    }
    mx = red[0];
    __syncthreads();
    float sum = 0.f;
#pragma unroll
    for (int r = 0; r < 4; r++) {
        v[r] = __expf(v[r] - mx);
        if (tid + r * 256 < T_) sum += v[r];
    }
    red[tid] = sum;
    __syncthreads();
    for (int off = 128; off > 0; off >>= 1) {
        if (tid < off) red[tid] += red[tid + off];
        __syncthreads();
    }
    float inv = 1.f / red[0];
#pragma unroll
    for (int r = 0; r < 4; r++) {
        int s = tid + r * 256;
        if (s < T_) P[s] = v[r] * inv;
    }
}

// ---------------------------------------------------------------------------
// O[bh,d,t] = sum_s V[bh,d,s] P[bh,t,s]
__global__ __launch_bounds__(256) void av_kernel() {
    __shared__ float Vs[16][65];
    __shared__ float Ps[16][65];
    const int bh = blockIdx.y;
    const int t0 = blockIdx.x * 64;
    const float* Vb = g_v + (size_t)bh * HEAD_ * T_;
    const float* Pb = g_p + (size_t)bh * T_ * T_;
    float* Ob = g_att + (size_t)bh * HEAD_ * T_;
    const int tid = threadIdx.x;
    const int tx = tid & 15, ty = tid >> 4;
    float acc[4][4] = {};
    for (int s0 = 0; s0 < T_; s0 += 16) {
        int ss = tid & 15, dq = tid >> 4;
#pragma unroll
        for (int r = 0; r < 4; r++) {
            int dd = dq + r * 16;
            Vs[ss][dd] = Vb[(size_t)dd * T_ + s0 + ss];
            int tt = t0 + dd;
            Ps[ss][dd] = (tt < T_) ? Pb[(size_t)tt * T_ + s0 + ss] : 0.f;
        }
        __syncthreads();
#pragma unroll
        for (int kk = 0; kk < 16; kk++) {
            float a[4], xv[4];
#pragma unroll
            for (int i = 0; i < 4; i++) a[i] = Vs[kk][ty * 4 + i];
#pragma unroll
            for (int j = 0; j < 4; j++) xv[j] = Ps[kk][tx * 4 + j];
#pragma unroll
            for (int i = 0; i < 4; i++)
#pragma unroll
                for (int j = 0; j < 4; j++) acc[i][j] += a[i] * xv[j];
        }
        __syncthreads();
    }
#pragma unroll
    for (int i = 0; i < 4; i++) {
        int d = ty * 4 + i;
#pragma unroll
        for (int j = 0; j < 4; j++) {
            int t = t0 + tx * 4 + j;
            if (t < T_) Ob[(size_t)d * T_ + t] = acc[i][j];
        }
    }
}

// ---------------------------------------------------------------------------
// O[bh,d,t] += sum_{j=0..8} P[bh,t,t+j-4] * ev[j,d]
__global__ __launch_bounds__(256) void addrelv_kernel(const float* __restrict__ ev) {
    __shared__ float pband[32][9];
    __shared__ float evs[9 * 64];
    const int bh = blockIdx.y;
    const int t0 = blockIdx.x * 32;
    const float* Pb = g_p + (size_t)bh * T_ * T_;
    float* Ob = g_att + (size_t)bh * HEAD_ * T_;
    const int tid = threadIdx.x;
    for (int idx = tid; idx < 9 * 64; idx += 256) evs[idx] = ev[idx];
    for (int idx = tid; idx < 32 * 9; idx += 256) {
        int tl = idx / 9, j = idx % 9;
        int t = t0 + tl, s = t + j - 4;
        pband[tl][j] = (t < T_ && s >= 0 && s < T_) ? Pb[(size_t)t * T_ + s] : 0.f;
    }
    __syncthreads();
    int tl = tid & 31, dg = tid >> 5;
    int t = t0 + tl;
    if (t >= T_) return;
#pragma unroll
    for (int dd = 0; dd < 8; dd++) {
        int d = dg * 8 + dd;
        float sum = 0.f;
#pragma unroll
        for (int j = 0; j < 9; j++) sum += pband[tl][j] * evs[j * 64 + d];
        Ob[(size_t)d * T_ + t] += sum;
    }
}

// ---------------------------------------------------------------------------
// h = LayerNorm_channels(h + Yadd) * g + be     (in-place on g_h)
__global__ void ln_kernel(const float* __restrict__ Yadd, const float* __restrict__ g,
                          const float* __restrict__ be) {
    const int b = blockIdx.y;
    const int tx = threadIdx.x;      // t lane (32)
    const int ty = threadIdx.y;      // c lane (8)
    const int t = blockIdx.x * 32 + tx;
    __shared__ float r1[8][32], r2[8][32];
    __shared__ float mu[32], wv[32];
    float s1 = 0.f, s2 = 0.f;
    if (t < T_) {
        for (int c = ty; c < H_; c += 8) {
            size_t off = (size_t)b * H_ * T_ + (size_t)c * T_ + t;
            float v = g_h[off] + Yadd[off];
            s1 += v; s2 += v * v;
        }
    }
    r1[ty][tx] = s1; r2[ty][tx] = s2;
    __syncthreads();
    if (ty == 0) {
        float a1 = 0.f, a2 = 0.f;
#pragma unroll
        for (int i = 0; i < 8; i++) { a1 += r1[i][tx]; a2 += r2[i][tx]; }
        float m = a1 / H_;
        float var = a2 / H_ - m * m;
        mu[tx] = m;
        wv[tx] = rsqrtf(var + 1e-5f);
    }
    __syncthreads();
    if (t < T_) {
        float m = mu[tx], ww = wv[tx];
        for (int c = ty; c < H_; c += 8) {
            size_t off = (size_t)b * H_ * T_ + (size_t)c * T_ + t;
            float v = g_h[off] + Yadd[off];
            g_h[off] = (v - m) * ww * g[c] + be[c];
        }
    }
}

// ---------------------------------------------------------------------------
// 1D conv KS=3, pad 1: Y[b,o,t] = sum_c sum_k W[o,c,k] * (X[b,c,t+k-1]*mask)
// 128(M) x 64(t) tile, 8x4 microtile. M must be multiple of 128.
__global__ __launch_bounds__(256) void conv_kernel(
    const float* __restrict__ W, const float* __restrict__ bias,
    const float* __restrict__ X, float* __restrict__ Y,
    const float* __restrict__ xm, int M, int C, int relu, int maskout)
{
    __shared__ float Ws[48][128];
    __shared__ float Xs[16][66];
    __shared__ float msk[66];
    const int b  = blockIdx.z;
    const int t0 = blockIdx.x * 64;
    const int m0 = blockIdx.y * 128;
    const int tid = threadIdx.x;
    const int tx = tid & 15, ty = tid >> 4;
    if (tid < 66) {
        int t = t0 - 1 + tid;
        msk[tid] = (t >= 0 && t < T_) ? xm[b * T_ + t] : 0.f;
    }
    __syncthreads();
    float acc[8][4] = {};
    const float* Xb = X + (size_t)b * C * T_;
    for (int c0 = 0; c0 < C; c0 += 16) {
        for (int idx = tid; idx < 128 * 48; idx += 256) {
            int o = idx / 48, ck = idx % 48;
            Ws[ck][o] = W[(size_t)(m0 + o) * C * 3 + (size_t)c0 * 3 + ck];
        }
        for (int idx = tid; idx < 16 * 66; idx += 256) {
            int c = idx / 66, col = idx % 66;
            int t = t0 - 1 + col;
            Xs[c][col] = (t >= 0 && t < T_) ? Xb[(size_t)(c0 + c) * T_ + t] * msk[col] : 0.f;
        }
        __syncthreads();
#pragma unroll
        for (int c = 0; c < 16; c++) {
            float xv[6];
#pragma unroll
            for (int u = 0; u < 6; u++) xv[u] = Xs[c][tx * 4 + u];
#pragma unroll
            for (int k = 0; k < 3; k++) {
                float a[8];
#pragma unroll
                for (int i = 0; i < 8; i++) a[i] = Ws[c * 3 + k][ty * 8 + i];
#pragma unroll
                for (int i = 0; i < 8; i++)
#pragma unroll
                    for (int j = 0; j < 4; j++) acc[i][j] += a[i] * xv[j + k];
            }
        }
        __syncthreads();
    }
#pragma unroll
    for (int i = 0; i < 8; i++) {
        int o = m0 + ty * 8 + i;
        float bb = bias[o];
#pragma unroll
        for (int j = 0; j < 4; j++) {
            int t = t0 + tx * 4 + j;
            if (t < T_) {
                float v = acc[i][j] + bb;
                if (relu) v = fmaxf(v, 0.f);
                if (maskout) v *= msk[1 + tx * 4 + j];
                Y[(size_t)b * M * T_ + (size_t)o * T_ + t] = v;
            }
        }
    }
}

// ---------------------------------------------------------------------------
// out = [mu_p ; logs_p] with mask, from prior (B, 2H, T)
__global__ void finalize_kernel(const float* __restrict__ prior, const float* __restrict__ xm,
                                float* __restrict__ out) {
    int idx = blockIdx.x * blockDim.x + threadIdx.x;
    const int total = B_ * 2 * H_ * T_;
    if (idx >= total) return;
    int t = idx % T_;
    int o = (idx / T_) % (2 * H_);
    int b = idx / (2 * H_ * T_);
    float v = prior[idx] * xm[b * T_ + t];
    size_t dst = (size_t)(o < H_ ? 0 : BHT_) + (size_t)b * H_ * T_ + (size_t)(o & (H_ - 1)) * T_ + t;
    out[dst] = v;
}

// ---------------------------------------------------------------------------
extern "C" void kernel_launch(void* const* d_in, const int* in_sizes, int n_in,
                              void* d_out, int out_size) {
    const float* x   = (const float*)d_in[0];
    const float* xm  = (const float*)d_in[1];
    const float* Wq  = (const float*)d_in[2];
    const float* bq  = (const float*)d_in[3];
    const float* Wk  = (const float*)d_in[4];
    const float* bk  = (const float*)d_in[5];
    const float* Wv  = (const float*)d_in[6];
    const float* bv  = (const float*)d_in[7];
    const float* Wo  = (const float*)d_in[8];
    const float* bo  = (const float*)d_in[9];
    const float* ek  = (const float*)d_in[10];
    const float* ev  = (const float*)d_in[11];
    const float* g1  = (const float*)d_in[12];
    const float* b1  = (const float*)d_in[13];
    const float* g2  = (const float*)d_in[14];
    const float* b2  = (const float*)d_in[15];
    const float* Wf1 = (const float*)d_in[16];
    const float* bf1 = (const float*)d_in[17];
    const float* Wf2 = (const float*)d_in[18];
    const float* bf2 = (const float*)d_in[19];
    const float* Wp  = (const float*)d_in[20];
    const float* bp  = (const float*)d_in[21];
    float* out = (float*)d_out;

    float *ph, *pq, *pk, *pv, *patt, *py, *pff;
    cudaGetSymbolAddress((void**)&ph,  g_h);
    cudaGetSymbolAddress((void**)&pq,  g_q);
    cudaGetSymbolAddress((void**)&pk,  g_k);
    cudaGetSymbolAddress((void**)&pv,  g_v);
    cudaGetSymbolAddress((void**)&patt, g_att);
    cudaGetSymbolAddress((void**)&py,  g_y);
    cudaGetSymbolAddress((void**)&pff, g_ff);

    const float scale = 0.125f;  // HEAD^{-1/2}
    const int TT = (T_ + 63) / 64;     // 13 time tiles
    const int TB32 = (T_ + 31) / 32;   // 25

    init_h_kernel<<<(BHT_ + 255) / 256, 256>>>(x, xm);

    for (int L = 0; L < NL_; L++) {
        const float* wq  = Wq  + (size_t)L * H_ * H_;
        const float* wk  = Wk  + (size_t)L * H_ * H_;
        const float* wv  = Wv  + (size_t)L * H_ * H_;
        const float* wo  = Wo  + (size_t)L * H_ * H_;
        const float* ekL = ek  + (size_t)L * 9 * HEAD_;
        const float* evL = ev  + (size_t)L * 9 * HEAD_;
        const float* wf1 = Wf1 + (size_t)L * FF_ * H_ * 3;
        const float* wf2 = Wf2 + (size_t)L * H_ * FF_ * 3;

        gemm_kernel<<<dim3(TT, H_ / 128, B_), 256>>>(wq, bq + L * H_, ph, pq, H_, H_);
        gemm_kernel<<<dim3(TT, H_ / 128, B_), 256>>>(wk, bk + L * H_, ph, pk, H_, H_);
        gemm_kernel<<<dim3(TT, H_ / 128, B_), 256>>>(wv, bv + L * H_, ph, pv, H_, H_);

        relk_kernel<<<(B_ * NH_ * T_ * 32 + 127) / 128, 128>>>(ekL, scale);
        scores_kernel<<<dim3(TT, TT, B_ * NH_), 256>>>(scale);
        softmax_kernel<<<B_ * NH_ * T_, 256>>>(xm);
        av_kernel<<<dim3(TT, B_ * NH_), 256>>>();
        addrelv_kernel<<<dim3(TB32, B_ * NH_), 256>>>(evL);

        gemm_kernel<<<dim3(TT, H_ / 128, B_), 256>>>(wo, bo + L * H_, patt, pq, H_, H_);
        ln_kernel<<<dim3(TB32, B_), dim3(32, 8)>>>(pq, g1 + L * H_, b1 + L * H_);

        conv_kernel<<<dim3(TT, FF_ / 128, B_), 256>>>(wf1, bf1 + L * FF_, ph, pff, xm, FF_, H_, 1, 0);
        conv_kernel<<<dim3(TT, H_ / 128, B_), 256>>>(wf2, bf2 + L * H_, pff, py, xm, H_, FF_, 0, 1);
        ln_kernel<<<dim3(TB32, B_), dim3(32, 8)>>>(py, g2 + L * H_, b2 + L * H_);
    }

    maskh_kernel<<<(BHT_ + 255) / 256, 256>>>(xm);
    gemm_kernel<<<dim3(TT, 2 * H_ / 128, B_), 256>>>(Wp, bp, ph, pff, 2 * H_, H_);
    finalize_kernel<<<(B_ * 2 * H_ * T_ + 255) / 256, 256>>>(pff, xm, out);
}

// round 3
// speedup vs baseline: 1.5031x; 1.5031x over previous
#include <cuda_runtime.h>
#include <math.h>
#include <stdint.h>

// ---------------------------------------------------------------------------
// FramePriorNetwork: 6-layer transformer (windowed rel-pos attention + conv FFN)
// Fixed shapes from setup_inputs. GEMM/conv on tensor cores (tf32 3-term split).
// ---------------------------------------------------------------------------
#define B_   4
#define T_   800
#define H_   512
#define FF_  2048
#define NH_  8
#define NL_  6
#define HEAD_ 64
#define BHT_ (B_ * H_ * T_)

// Scratch (device globals: allocation-free rule)
__device__ float g_h[BHT_];
__device__ float g_q[BHT_];
__device__ float g_k[BHT_];
__device__ float g_v[BHT_];
__device__ float g_att[BHT_];
__device__ float g_y[BHT_];
__device__ float g_p[(size_t)B_ * NH_ * T_ * T_];      // scores / probs, ~82 MB
__device__ float g_rl[B_ * NH_ * T_ * 9];              // banded rel-k logits
__device__ float g_ff[B_ * FF_ * T_];                  // FFN hidden / final prior

// ---------------------------------------------------------------------------
__global__ void init_h_kernel(const float* __restrict__ x, const float* __restrict__ xm) {
    int idx = blockIdx.x * blockDim.x + threadIdx.x;
    if (idx >= BHT_) return;
    int t = idx % T_;
    int b = idx / (H_ * T_);
    g_h[idx] = x[idx] * xm[b * T_ + t];
}

__global__ void maskh_kernel(const float* __restrict__ xm) {
    int idx = blockIdx.x * blockDim.x + threadIdx.x;
    if (idx >= BHT_) return;
    int t = idx % T_;
    int b = idx / (H_ * T_);
    g_h[idx] *= xm[b * T_ + t];
}

// ---------------------------------------------------------------------------
// tf32 mma helpers
__device__ __forceinline__ void mma_tf32(float* d, const uint32_t* a, const uint32_t* b) {
    asm volatile(
        "mma.sync.aligned.m16n8k8.row.col.f32.tf32.tf32.f32 "
        "{%0,%1,%2,%3}, {%4,%5,%6,%7}, {%8,%9}, {%0,%1,%2,%3};\n"
        : "+f"(d[0]), "+f"(d[1]), "+f"(d[2]), "+f"(d[3])
        : "r"(a[0]), "r"(a[1]), "r"(a[2]), "r"(a[3]), "r"(b[0]), "r"(b[1]));
}
__device__ __forceinline__ void split_tf32(float v, uint32_t& hi, uint32_t& lo) {
    uint32_t u = __float_as_uint(v);
    hi = u & 0xffffe000u;
    lo = __float_as_uint(v - __uint_as_float(hi));
}

// ---------------------------------------------------------------------------
// Tensor-core GEMM: Y[b,m,t] = sum_c W[m,c] X[b,c,t] + bias[m]
// Tile: 128(M) x 64(t), BK=32. 256 threads = 8 warps, warp tile 32x32.
// Requires M % 128 == 0, K % 32 == 0.
#define GW_S 36   // Ws[m][GW_S]  (36 mod 32 == 4 -> conflict-free frag loads)
#define GX_S 72   // Xs[k][GX_S]  (72 mod 32 == 8)
__global__ __launch_bounds__(256) void gemm_tc_kernel(
    const float* __restrict__ W, const float* __restrict__ bias,
    const float* __restrict__ X, float* __restrict__ Y, int M, int K)
{
    __shared__ float Ws[128 * GW_S];
    __shared__ float Xs[32 * GX_S];
    const int b  = blockIdx.z;
    const int t0 = blockIdx.x * 64;
    const int m0 = blockIdx.y * 128;
    const float* Xb = X + (size_t)b * K * T_;
    float* Yb = Y + (size_t)b * M * T_;
    const int tid  = threadIdx.x;
    const int lane = tid & 31;
    const int w    = tid >> 5;
    const int wm   = w >> 1;        // 0..3
    const int wn   = w & 1;         // 0..1
    const int lq   = lane >> 2;     // 0..7
    const int lr   = lane & 3;      // 0..3

    float acc[2][4][4];
#pragma unroll
    for (int i = 0; i < 2; i++)
#pragma unroll
        for (int j = 0; j < 4; j++)
#pragma unroll
            for (int r = 0; r < 4; r++) acc[i][j][r] = 0.f;

    for (int k0 = 0; k0 < K; k0 += 32) {
        // W tile: 128 x 32, gmem coalesced, smem conflict-free
#pragma unroll
        for (int it = 0; it < 16; it++) {
            int idx = tid + it * 256;
            int kk = idx & 31, m = idx >> 5;
            Ws[m * GW_S + kk] = W[(size_t)(m0 + m) * K + (k0 + kk)];
        }
        // X tile: 32 x 64
#pragma unroll
        for (int it = 0; it < 8; it++) {
            int idx = tid + it * 256;
            int t = idx & 63, kk = idx >> 6;
            int tg = t0 + t;
            Xs[kk * GX_S + t] = (tg < T_) ? Xb[(size_t)(k0 + kk) * T_ + tg] : 0.f;
        }
        __syncthreads();
#pragma unroll
        for (int ks = 0; ks < 4; ks++) {
            const int kb = ks * 8;
            uint32_t ahi[2][4], alo[2][4], bhi[4][2], blo[4][2];
#pragma unroll
            for (int i = 0; i < 2; i++) {
                int row = wm * 32 + i * 16 + lq;
                int col = kb + lr;
                split_tf32(Ws[row * GW_S + col],           ahi[i][0], alo[i][0]);
                split_tf32(Ws[(row + 8) * GW_S + col],     ahi[i][1], alo[i][1]);
                split_tf32(Ws[row * GW_S + col + 4],       ahi[i][2], alo[i][2]);
                split_tf32(Ws[(row + 8) * GW_S + col + 4], ahi[i][3], alo[i][3]);
            }
#pragma unroll
            for (int j = 0; j < 4; j++) {
                int tt = wn * 32 + j * 8 + lq;
                split_tf32(Xs[(kb + lr) * GX_S + tt],     bhi[j][0], blo[j][0]);
                split_tf32(Xs[(kb + 4 + lr) * GX_S + tt], bhi[j][1], blo[j][1]);
            }
#pragma unroll
            for (int j = 0; j < 4; j++)
#pragma unroll
                for (int i = 0; i < 2; i++) {
                    mma_tf32(acc[i][j], ahi[i], bhi[j]);
                    mma_tf32(acc[i][j], alo[i], bhi[j]);
                    mma_tf32(acc[i][j], ahi[i], blo[j]);
                }
        }
        __syncthreads();
    }
    // epilogue
#pragma unroll
    for (int i = 0; i < 2; i++) {
        int r0 = m0 + wm * 32 + i * 16 + lq;
        float b0 = bias[r0], b1 = bias[r0 + 8];
#pragma unroll
        for (int j = 0; j < 4; j++) {
            int t = t0 + wn * 32 + j * 8 + 2 * lr;
            if (t >= T_) continue;
            float2 v0 = make_float2(acc[i][j][0] + b0, acc[i][j][1] + b0);
            float2 v1 = make_float2(acc[i][j][2] + b1, acc[i][j][3] + b1);
            *(float2*)&Yb[(size_t)r0 * T_ + t] = v0;
            *(float2*)&Yb[(size_t)(r0 + 8) * T_ + t] = v1;
        }
    }
}

// ---------------------------------------------------------------------------
// Tensor-core conv1d KS=3 pad 1: Y[b,o,t] = sum_{c,kk} W[o,c,kk]*(X[b,c,t+kk-1]*m)
// Tile 128(o) x 64(t), c-block 16 (k-extent 48 = 16c x 3taps via smem im2col).
#define CW_S 52   // Ws[o][CW_S] (52 mod 32 == 20 -> conflict-free)
#define CX_S 72
__global__ __launch_bounds__(256) void conv_tc_kernel(
    const float* __restrict__ W, const float* __restrict__ bias,
    const float* __restrict__ X, float* __restrict__ Y,
    const float* __restrict__ xm, int M, int C, int relu, int maskout)
{
    __shared__ float Ws[128 * CW_S];
    __shared__ float Xs[48 * CX_S];
    __shared__ float msk[66];
    const int b  = blockIdx.z;
    const int t0 = blockIdx.x * 64;
    const int m0 = blockIdx.y * 128;
    const int tid  = threadIdx.x;
    const int lane = tid & 31;
    const int w    = tid >> 5;
    const int wm   = w >> 1;
    const int wn   = w & 1;
    const int lq   = lane >> 2;
    const int lr   = lane & 3;

    if (tid < 66) {
        int t = t0 - 1 + tid;
        msk[tid] = (t >= 0 && t < T_) ? xm[b * T_ + t] : 0.f;
    }

    float acc[2][4][4];
#pragma unroll
    for (int i = 0; i < 2; i++)
#pragma unroll
        for (int j = 0; j < 4; j++)
#pragma unroll
            for (int r = 0; r < 4; r++) acc[i][j][r] = 0.f;

    const float* Xb = X + (size_t)b * C * T_;
    __syncthreads();

    for (int c0 = 0; c0 < C; c0 += 16) {
        // W tile: 128 x 48 (ck = c*3+kk contiguous in gmem)
#pragma unroll
        for (int it = 0; it < 24; it++) {
            int idx = tid + it * 256;
            int ck = idx % 48, o = idx / 48;
            Ws[o * CW_S + ck] = W[(size_t)(m0 + o) * C * 3 + (size_t)c0 * 3 + ck];
        }
        // im2col X tile: 48 x 64
#pragma unroll
        for (int it = 0; it < 12; it++) {
            int idx = tid + it * 256;
            int t = idx & 63, ck = idx >> 6;
            int c = ck / 3, kk = ck % 3;
            int tg = t0 + t + kk - 1;
            float v = 0.f;
            if (tg >= 0 && tg < T_) v = Xb[(size_t)(c0 + c) * T_ + tg] * msk[t + kk];
            Xs[ck * CX_S + t] = v;
        }
        __syncthreads();
#pragma unroll
        for (int ks = 0; ks < 6; ks++) {
            const int kb = ks * 8;
            uint32_t ahi[2][4], alo[2][4], bhi[4][2], blo[4][2];
#pragma unroll
            for (int i = 0; i < 2; i++) {
                int row = wm * 32 + i * 16 + lq;
                int col = kb + lr;
                split_tf32(Ws[row * CW_S + col],           ahi[i][0], alo[i][0]);
                split_tf32(Ws[(row + 8) * CW_S + col],     ahi[i][1], alo[i][1]);
                split_tf32(Ws[row * CW_S + col + 4],       ahi[i][2], alo[i][2]);
                split_tf32(Ws[(row + 8) * CW_S + col + 4], ahi[i][3], alo[i][3]);
            }
#pragma unroll
            for (int j = 0; j < 4; j++) {
                int tt = wn * 32 + j * 8 + lq;
                split_tf32(Xs[(kb + lr) * CX_S + tt],     bhi[j][0], blo[j][0]);
                split_tf32(Xs[(kb + 4 + lr) * CX_S + tt], bhi[j][1], blo[j][1]);
            }
#pragma unroll
            for (int j = 0; j < 4; j++)
#pragma unroll
                for (int i = 0; i < 2; i++) {
                    mma_tf32(acc[i][j], ahi[i], bhi[j]);
                    mma_tf32(acc[i][j], alo[i], bhi[j]);
                    mma_tf32(acc[i][j], ahi[i], blo[j]);
                }
        }
        __syncthreads();
    }
    // epilogue
#pragma unroll
    for (int i = 0; i < 2; i++) {
        int r0 = m0 + wm * 32 + i * 16 + lq;
        float bb0 = bias[r0], bb1 = bias[r0 + 8];
#pragma unroll
        for (int j = 0; j < 4; j++) {
            int t = t0 + wn * 32 + j * 8 + 2 * lr;
            if (t >= T_) continue;
            float v00 = acc[i][j][0] + bb0, v01 = acc[i][j][1] + bb0;
            float v10 = acc[i][j][2] + bb1, v11 = acc[i][j][3] + bb1;
            if (relu) {
                v00 = fmaxf(v00, 0.f); v01 = fmaxf(v01, 0.f);
                v10 = fmaxf(v10, 0.f); v11 = fmaxf(v11, 0.f);
            }
            if (maskout) {
                float mk0 = msk[1 + wn * 32 + j * 8 + 2 * lr];
                float mk1 = msk[1 + wn * 32 + j * 8 + 2 * lr + 1];
                v00 *= mk0; v01 *= mk1; v10 *= mk0; v11 *= mk1;
            }
            *(float2*)&Y[(size_t)b * M * T_ + (size_t)r0 * T_ + t] = make_float2(v00, v01);
            *(float2*)&Y[(size_t)b * M * T_ + (size_t)(r0 + 8) * T_ + t] = make_float2(v10, v11);
        }
    }
}

// ---------------------------------------------------------------------------
// S[bh,t,s] = scale * sum_d Q[bh,d,t] K[bh,d,s]
__global__ __launch_bounds__(256) void scores_kernel(float scale) {
    __shared__ float Qs[16][64];
    __shared__ float Ks[16][64];
    const int bh = blockIdx.z;
    const int s0 = blockIdx.x * 64;
    const int t0 = blockIdx.y * 64;
    const float* Qb = g_q + (size_t)bh * HEAD_ * T_;
    const float* Kb = g_k + (size_t)bh * HEAD_ * T_;
    float* Sb = g_p + (size_t)bh * T_ * T_;
    const int tid = threadIdx.x;
    const int tx = tid & 15, ty = tid >> 4;
    float acc[4][4] = {};
    for (int k0 = 0; k0 < HEAD_; k0 += 16) {
        int col = tid & 63, rq = tid >> 6;
#pragma unroll
        for (int r = 0; r < 4; r++) {
            int kk = r * 4 + rq;
            int t = t0 + col;
            Qs[kk][col] = (t < T_) ? Qb[(size_t)(k0 + kk) * T_ + t] : 0.f;
            int s = s0 + col;
            Ks[kk][col] = (s < T_) ? Kb[(size_t)(k0 + kk) * T_ + s] : 0.f;
        }
        __syncthreads();
#pragma unroll
        for (int kk = 0; kk < 16; kk++) {
            float a[4], xv[4];
#pragma unroll
            for (int i = 0; i < 4; i++) a[i] = Qs[kk][ty * 4 + i];
#pragma unroll
            for (int j = 0; j < 4; j++) xv[j] = Ks[kk][tx * 4 + j];
#pragma unroll
            for (int i = 0; i < 4; i++)
#pragma unroll
                for (int j = 0; j < 4; j++) acc[i][j] += a[i] * xv[j];
        }
        __syncthreads();
    }
#pragma unroll
    for (int i = 0; i < 4; i++) {
        int t = t0 + ty * 4 + i;
        if (t >= T_) continue;
#pragma unroll
        for (int j = 0; j < 4; j++) {
            int s = s0 + tx * 4 + j;
            if (s < T_) Sb[(size_t)t * T_ + s] = acc[i][j] * scale;
        }
    }
}

// ---------------------------------------------------------------------------
__global__ void relk_kernel(const float* __restrict__ ek, float scale) {
    int w = (blockIdx.x * blockDim.x + threadIdx.x) >> 5;
    int lane = threadIdx.x & 31;
    if (w >= B_ * NH_ * T_) return;
    int bh = w / T_, t = w % T_;
    const float* qb = g_q + (size_t)bh * HEAD_ * T_ + t;
    float q0 = qb[(size_t)lane * T_] * scale;
    float q1 = qb[(size_t)(lane + 32) * T_] * scale;
#pragma unroll
    for (int j = 0; j < 9; j++) {
        float v = q0 * ek[j * HEAD_ + lane] + q1 * ek[j * HEAD_ + lane + 32];
#pragma unroll
        for (int off = 16; off > 0; off >>= 1) v += __shfl_down_sync(0xffffffffu, v, off);
        if (lane == 0) g_rl[w * 9 + j] = v;
    }
}

// ---------------------------------------------------------------------------
__global__ __launch_bounds__(256) void softmax_kernel(const float* __restrict__ xm) {
    const int row = blockIdx.x;
    const int bh = row / T_, t = row % T_;
    const int b = bh / NH_;
    float* P = g_p + (size_t)bh * T_ * T_ + (size_t)t * T_;
    const float* rl = g_rl + (size_t)row * 9;
    const float mt = xm[b * T_ + t];
    const int tid = threadIdx.x;
    float v[4];
#pragma unroll
    for (int r = 0; r < 4; r++) {
        int s = tid + r * 256;
        float val = -1e30f;
        if (s < T_) {
            val = P[s];
            int j = s - t + 4;
            if (j >= 0 && j < 9) val += rl[j];
            if (mt == 0.f || xm[b * T_ + s] == 0.f) val = -10000.0f;
        }
        v[r] = val;
    }
    __shared__ float red[256];
    float mx = fmaxf(fmaxf(v[0], v[1]), fmaxf(v[2], v[3]));
    red[tid] = mx;
    __syncthreads();
    for (int off = 128; off > 0; off >>= 1) {
        if (tid < off) red[tid] = fmaxf(red[tid], red[tid + off]);
        __syncthreads();
    }
    mx = red[0];
    __syncthreads();
    float sum = 0.f;
#pragma unroll
    for (int r = 0; r < 4; r++) {
        v[r] = __expf(v[r] - mx);
        if (tid + r * 256 < T_) sum += v[r];
    }
    red[tid] = sum;
    __syncthreads();
    for (int off = 128; off > 0; off >>= 1) {
        if (tid < off) red[tid] += red[tid + off];
        __syncthreads();
    }
    float inv = 1.f / red[0];
#pragma unroll
    for (int r = 0; r < 4; r++) {
        int s = tid + r * 256;
        if (s < T_) P[s] = v[r] * inv;
    }
}

// ---------------------------------------------------------------------------
__global__ __launch_bounds__(256) void av_kernel() {
    __shared__ float Vs[16][65];
    __shared__ float Ps[16][65];
    const int bh = blockIdx.y;
    const int t0 = blockIdx.x * 64;
    const float* Vb = g_v + (size_t)bh * HEAD_ * T_;
    const float* Pb = g_p + (size_t)bh * T_ * T_;
    float* Ob = g_att + (size_t)bh * HEAD_ * T_;
    const int tid = threadIdx.x;
    const int tx = tid & 15, ty = tid >> 4;
    float acc[4][4] = {};
    for (int s0 = 0; s0 < T_; s0 += 16) {
        int ss = tid & 15, dq = tid >> 4;
#pragma unroll
        for (int r = 0; r < 4; r++) {
            int dd = dq + r * 16;
            Vs[ss][dd] = Vb[(size_t)dd * T_ + s0 + ss];
            int tt = t0 + dd;
            Ps[ss][dd] = (tt < T_) ? Pb[(size_t)tt * T_ + s0 + ss] : 0.f;
        }
        __syncthreads();
#pragma unroll
        for (int kk = 0; kk < 16; kk++) {
            float a[4], xv[4];
#pragma unroll
            for (int i = 0; i < 4; i++) a[i] = Vs[kk][ty * 4 + i];
#pragma unroll
            for (int j = 0; j < 4; j++) xv[j] = Ps[kk][tx * 4 + j];
#pragma unroll
            for (int i = 0; i < 4; i++)
#pragma unroll
                for (int j = 0; j < 4; j++) acc[i][j] += a[i] * xv[j];
        }
        __syncthreads();
    }
#pragma unroll
    for (int i = 0; i < 4; i++) {
        int d = ty * 4 + i;
#pragma unroll
        for (int j = 0; j < 4; j++) {
            int t = t0 + tx * 4 + j;
            if (t < T_) Ob[(size_t)d * T_ + t] = acc[i][j];
        }
    }
}

// ---------------------------------------------------------------------------
__global__ __launch_bounds__(256) void addrelv_kernel(const float* __restrict__ ev) {
    __shared__ float pband[32][9];
    __shared__ float evs[9 * 64];
    const int bh = blockIdx.y;
    const int t0 = blockIdx.x * 32;
    const float* Pb = g_p + (size_t)bh * T_ * T_;
    float* Ob = g_att + (size_t)bh * HEAD_ * T_;
    const int tid = threadIdx.x;
    for (int idx = tid; idx < 9 * 64; idx += 256) evs[idx] = ev[idx];
    for (int idx = tid; idx < 32 * 9; idx += 256) {
        int tl = idx / 9, j = idx % 9;
        int t = t0 + tl, s = t + j - 4;
        pband[tl][j] = (t < T_ && s >= 0 && s < T_) ? Pb[(size_t)t * T_ + s] : 0.f;
    }
    __syncthreads();
    int tl = tid & 31, dg = tid >> 5;
    int t = t0 + tl;
    if (t >= T_) return;
#pragma unroll
    for (int dd = 0; dd < 8; dd++) {
        int d = dg * 8 + dd;
        float sum = 0.f;
#pragma unroll
        for (int j = 0; j < 9; j++) sum += pband[tl][j] * evs[j * 64 + d];
        Ob[(size_t)d * T_ + t] += sum;
    }
}

// ---------------------------------------------------------------------------
__global__ void ln_kernel(const float* __restrict__ Yadd, const float* __restrict__ g,
                          const float* __restrict__ be) {
    const int b = blockIdx.y;
    const int tx = threadIdx.x;
    const int ty = threadIdx.y;
    const int t = blockIdx.x * 32 + tx;
    __shared__ float r1[8][32], r2[8][32];
    __shared__ float mu[32], wv[32];
    float s1 = 0.f, s2 = 0.f;
    if (t < T_) {
        for (int c = ty; c < H_; c += 8) {
            size_t off = (size_t)b * H_ * T_ + (size_t)c * T_ + t;
            float v = g_h[off] + Yadd[off];
            s1 += v; s2 += v * v;
        }
    }
    r1[ty][tx] = s1; r2[ty][tx] = s2;
    __syncthreads();
    if (ty == 0) {
        float a1 = 0.f, a2 = 0.f;
#pragma unroll
        for (int i = 0; i < 8; i++) { a1 += r1[i][tx]; a2 += r2[i][tx]; }
        float m = a1 / H_;
        float var = a2 / H_ - m * m;
        mu[tx] = m;
        wv[tx] = rsqrtf(var + 1e-5f);
    }
    __syncthreads();
    if (t < T_) {
        float m = mu[tx], ww = wv[tx];
        for (int c = ty; c < H_; c += 8) {
            size_t off = (size_t)b * H_ * T_ + (size_t)c * T_ + t;
            float v = g_h[off] + Yadd[off];
            g_h[off] = (v - m) * ww * g[c] + be[c];
        }
    }
}

// ---------------------------------------------------------------------------
__global__ void finalize_kernel(const float* __restrict__ prior, const float* __restrict__ xm,
                                float* __restrict__ out) {
    int idx = blockIdx.x * blockDim.x + threadIdx.x;
    const int total = B_ * 2 * H_ * T_;
    if (idx >= total) return;
    int t = idx % T_;
    int o = (idx / T_) % (2 * H_);
    int b = idx / (2 * H_ * T_);
    float v = prior[idx] * xm[b * T_ + t];
    size_t dst = (size_t)(o < H_ ? 0 : BHT_) + (size_t)b * H_ * T_ + (size_t)(o & (H_ - 1)) * T_ + t;
    out[dst] = v;
}

// ---------------------------------------------------------------------------
extern "C" void kernel_launch(void* const* d_in, const int* in_sizes, int n_in,
                              void* d_out, int out_size) {
    const float* x   = (const float*)d_in[0];
    const float* xm  = (const float*)d_in[1];
    const float* Wq  = (const float*)d_in[2];
    const float* bq  = (const float*)d_in[3];
    const float* Wk  = (const float*)d_in[4];
    const float* bk  = (const float*)d_in[5];
    const float* Wv  = (const float*)d_in[6];
    const float* bv  = (const float*)d_in[7];
    const float* Wo  = (const float*)d_in[8];
    const float* bo  = (const float*)d_in[9];
    const float* ek  = (const float*)d_in[10];
    const float* ev  = (const float*)d_in[11];
    const float* g1  = (const float*)d_in[12];
    const float* b1  = (const float*)d_in[13];
    const float* g2  = (const float*)d_in[14];
    const float* b2  = (const float*)d_in[15];
    const float* Wf1 = (const float*)d_in[16];
    const float* bf1 = (const float*)d_in[17];
    const float* Wf2 = (const float*)d_in[18];
    const float* bf2 = (const float*)d_in[19];
    const float* Wp  = (const float*)d_in[20];
    const float* bp  = (const float*)d_in[21];
    float* out = (float*)d_out;

    float *ph, *pq, *pk, *pv, *patt, *py, *pff;
    cudaGetSymbolAddress((void**)&ph,  g_h);
    cudaGetSymbolAddress((void**)&pq,  g_q);
    cudaGetSymbolAddress((void**)&pk,  g_k);
    cudaGetSymbolAddress((void**)&pv,  g_v);
    cudaGetSymbolAddress((void**)&patt, g_att);
    cudaGetSymbolAddress((void**)&py,  g_y);
    cudaGetSymbolAddress((void**)&pff, g_ff);

    const float scale = 0.125f;  // HEAD^{-1/2}
    const int TT = (T_ + 63) / 64;     // 13 time tiles
    const int TB32 = (T_ + 31) / 32;   // 25

    init_h_kernel<<<(BHT_ + 255) / 256, 256>>>(x, xm);

    for (int L = 0; L < NL_; L++) {
        const float* wq  = Wq  + (size_t)L * H_ * H_;
        const float* wk  = Wk  + (size_t)L * H_ * H_;
        const float* wv  = Wv  + (size_t)L * H_ * H_;
        const float* wo  = Wo  + (size_t)L * H_ * H_;
        const float* ekL = ek  + (size_t)L * 9 * HEAD_;
        const float* evL = ev  + (size_t)L * 9 * HEAD_;
        const float* wf1 = Wf1 + (size_t)L * FF_ * H_ * 3;
        const float* wf2 = Wf2 + (size_t)L * H_ * FF_ * 3;

        gemm_tc_kernel<<<dim3(TT, H_ / 128, B_), 256>>>(wq, bq + L * H_, ph, pq, H_, H_);
        gemm_tc_kernel<<<dim3(TT, H_ / 128, B_), 256>>>(wk, bk + L * H_, ph, pk, H_, H_);
        gemm_tc_kernel<<<dim3(TT, H_ / 128, B_), 256>>>(wv, bv + L * H_, ph, pv, H_, H_);

        relk_kernel<<<(B_ * NH_ * T_ * 32 + 127) / 128, 128>>>(ekL, scale);
        scores_kernel<<<dim3(TT, TT, B_ * NH_), 256>>>(scale);
        softmax_kernel<<<B_ * NH_ * T_, 256>>>(xm);
        av_kernel<<<dim3(TT, B_ * NH_), 256>>>();
        addrelv_kernel<<<dim3(TB32, B_ * NH_), 256>>>(evL);

        gemm_tc_kernel<<<dim3(TT, H_ / 128, B_), 256>>>(wo, bo + L * H_, patt, pq, H_, H_);
        ln_kernel<<<dim3(TB32, B_), dim3(32, 8)>>>(pq, g1 + L * H_, b1 + L * H_);

        conv_tc_kernel<<<dim3(TT, FF_ / 128, B_), 256>>>(wf1, bf1 + L * FF_, ph, pff, xm, FF_, H_, 1, 0);
        conv_tc_kernel<<<dim3(TT, H_ / 128, B_), 256>>>(wf2, bf2 + L * H_, pff, py, xm, H_, FF_, 0, 1);
        ln_kernel<<<dim3(TB32, B_), dim3(32, 8)>>>(py, g2 + L * H_, b2 + L * H_);
    }

    maskh_kernel<<<(BHT_ + 255) / 256, 256>>>(xm);
    gemm_tc_kernel<<<dim3(TT, 2 * H_ / 128, B_), 256>>>(Wp, bp, ph, pff, 2 * H_, H_);
    finalize_kernel<<<(B_ * 2 * H_ * T_ + 255) / 256, 256>>>(pff, xm, out);
}

// round 4
// speedup vs baseline: 1.7993x; 1.1971x over previous
#include <cuda_runtime.h>
#include <math.h>
#include <stdint.h>

// ---------------------------------------------------------------------------
// FramePriorNetwork. Fixed shapes. All heavy math on tensor cores
// (tf32 3-term split ~= fp32 accuracy).
// ---------------------------------------------------------------------------
#define B_   4
#define T_   800
#define H_   512
#define FF_  2048
#define NH_  8
#define NL_  6
#define HEAD_ 64
#define BHT_ (B_ * H_ * T_)

__device__ float g_h[BHT_];
__device__ float g_q[BHT_];
__device__ float g_k[BHT_];
__device__ float g_v[BHT_];
__device__ float g_att[BHT_];
__device__ float g_y[BHT_];
__device__ float g_p[(size_t)B_ * NH_ * T_ * T_];
__device__ float g_rl[B_ * NH_ * T_ * 9];
__device__ float g_ff[B_ * FF_ * T_];

// ---------------------------------------------------------------------------
__global__ void init_h_kernel(const float* __restrict__ x, const float* __restrict__ xm) {
    int idx = blockIdx.x * blockDim.x + threadIdx.x;
    if (idx >= BHT_) return;
    int t = idx % T_;
    int b = idx / (H_ * T_);
    g_h[idx] = x[idx] * xm[b * T_ + t];
}
__global__ void maskh_kernel(const float* __restrict__ xm) {
    int idx = blockIdx.x * blockDim.x + threadIdx.x;
    if (idx >= BHT_) return;
    int t = idx % T_;
    int b = idx / (H_ * T_);
    g_h[idx] *= xm[b * T_ + t];
}

// ---------------------------------------------------------------------------
__device__ __forceinline__ void mma_tf32(float* d, const uint32_t* a, const uint32_t* b) {
    asm volatile(
        "mma.sync.aligned.m16n8k8.row.col.f32.tf32.tf32.f32 "
        "{%0,%1,%2,%3}, {%4,%5,%6,%7}, {%8,%9}, {%0,%1,%2,%3};\n"
        : "+f"(d[0]), "+f"(d[1]), "+f"(d[2]), "+f"(d[3])
        : "r"(a[0]), "r"(a[1]), "r"(a[2]), "r"(a[3]), "r"(b[0]), "r"(b[1]));
}
__device__ __forceinline__ void split_tf32(float v, uint32_t& hi, uint32_t& lo) {
    uint32_t u = __float_as_uint(v);
    hi = u & 0xffffe000u;
    lo = __float_as_uint(v - __uint_as_float(hi));
}

// ---------------------------------------------------------------------------
// Shared GEMM core: Y[m,t] = sum_k W[m,k] X[k,t] + bias[m]
// CTA tile 128(M)x64(t), BK=32, 8 warps (4x2), warp tile 32x32.
#define GW_S 36
#define GX_S 72
__device__ __forceinline__ void gemm_core(
    const float* __restrict__ W, const float* __restrict__ bias,
    const float* __restrict__ Xb, float* __restrict__ Yb,
    int K, int t0, int m0)
{
    __shared__ float Ws[128 * GW_S];
    __shared__ float Xs[32 * GX_S];
    const int tid  = threadIdx.x;
    const int lane = tid & 31;
    const int w    = tid >> 5;
    const int wm   = w >> 1;
    const int wn   = w & 1;
    const int lq   = lane >> 2;
    const int lr   = lane & 3;

    float acc[2][4][4];
#pragma unroll
    for (int i = 0; i < 2; i++)
#pragma unroll
        for (int j = 0; j < 4; j++)
#pragma unroll
            for (int r = 0; r < 4; r++) acc[i][j][r] = 0.f;

    for (int k0 = 0; k0 < K; k0 += 32) {
#pragma unroll
        for (int it = 0; it < 16; it++) {
            int idx = tid + it * 256;
            int kk = idx & 31, m = idx >> 5;
            Ws[m * GW_S + kk] = W[(size_t)(m0 + m) * K + (k0 + kk)];
        }
#pragma unroll
        for (int it = 0; it < 8; it++) {
            int idx = tid + it * 256;
            int t = idx & 63, kk = idx >> 6;
            int tg = t0 + t;
            Xs[kk * GX_S + t] = (tg < T_) ? Xb[(size_t)(k0 + kk) * T_ + tg] : 0.f;
        }
        __syncthreads();
#pragma unroll
        for (int ks = 0; ks < 4; ks++) {
            const int kb = ks * 8;
            uint32_t ahi[2][4], alo[2][4];
#pragma unroll
            for (int i = 0; i < 2; i++) {
                int row = wm * 32 + i * 16 + lq;
                int col = kb + lr;
                split_tf32(Ws[row * GW_S + col],           ahi[i][0], alo[i][0]);
                split_tf32(Ws[(row + 8) * GW_S + col],     ahi[i][1], alo[i][1]);
                split_tf32(Ws[row * GW_S + col + 4],       ahi[i][2], alo[i][2]);
                split_tf32(Ws[(row + 8) * GW_S + col + 4], ahi[i][3], alo[i][3]);
            }
#pragma unroll
            for (int j = 0; j < 4; j++) {
                int tt = wn * 32 + j * 8 + lq;
                uint32_t bhi[2], blo[2];
                split_tf32(Xs[(kb + lr) * GX_S + tt],     bhi[0], blo[0]);
                split_tf32(Xs[(kb + 4 + lr) * GX_S + tt], bhi[1], blo[1]);
#pragma unroll
                for (int i = 0; i < 2; i++) {
                    mma_tf32(acc[i][j], ahi[i], bhi);
                    mma_tf32(acc[i][j], alo[i], bhi);
                    mma_tf32(acc[i][j], ahi[i], blo);
                }
            }
        }
        __syncthreads();
    }
#pragma unroll
    for (int i = 0; i < 2; i++) {
        int r0 = m0 + wm * 32 + i * 16 + lq;
        float b0 = bias[r0], b1 = bias[r0 + 8];
#pragma unroll
        for (int j = 0; j < 4; j++) {
            int t = t0 + wn * 32 + j * 8 + 2 * lr;
            if (t >= T_) continue;
            *(float2*)&Yb[(size_t)r0 * T_ + t] = make_float2(acc[i][j][0] + b0, acc[i][j][1] + b0);
            *(float2*)&Yb[(size_t)(r0 + 8) * T_ + t] = make_float2(acc[i][j][2] + b1, acc[i][j][3] + b1);
        }
    }
}

__global__ __launch_bounds__(256, 2) void gemm_tc_kernel(
    const float* __restrict__ W, const float* __restrict__ bias,
    const float* __restrict__ X, float* __restrict__ Y, int M, int K)
{
    const int b = blockIdx.z;
    gemm_core(W, bias, X + (size_t)b * K * T_, Y + (size_t)b * M * T_,
              K, blockIdx.x * 64, blockIdx.y * 128);
}

// Fused Q/K/V projections: blockIdx.y in [0,12): sel = y>>2 picks matrix.
__global__ __launch_bounds__(256, 2) void gemm3_tc_kernel(
    const float* __restrict__ Wq, const float* __restrict__ bq, float* __restrict__ Yq,
    const float* __restrict__ Wk, const float* __restrict__ bk, float* __restrict__ Yk,
    const float* __restrict__ Wv, const float* __restrict__ bv, float* __restrict__ Yv,
    const float* __restrict__ X)
{
    const int b = blockIdx.z;
    const int sel = blockIdx.y >> 2;
    const int m0 = (blockIdx.y & 3) * 128;
    const float* W = (sel == 0) ? Wq : (sel == 1) ? Wk : Wv;
    const float* bias = (sel == 0) ? bq : (sel == 1) ? bk : bv;
    float* Y = (sel == 0) ? Yq : (sel == 1) ? Yk : Yv;
    gemm_core(W, bias, X + (size_t)b * H_ * T_, Y + (size_t)b * H_ * T_, H_, blockIdx.x * 64, m0);
}

// ---------------------------------------------------------------------------
// Conv1d KS=3 pad 1 on tensor cores. Tile 128(o) x 64(t), c-block 16 (k=48).
#define CW_S 52
#define CX_S 72
__global__ __launch_bounds__(256, 2) void conv_tc_kernel(
    const float* __restrict__ W, const float* __restrict__ bias,
    const float* __restrict__ X, float* __restrict__ Y,
    const float* __restrict__ xm, int M, int C, int relu, int maskout)
{
    __shared__ float Ws[128 * CW_S];
    __shared__ float Xs[48 * CX_S];
    __shared__ float msk[66];
    const int b  = blockIdx.z;
    const int t0 = blockIdx.x * 64;
    const int m0 = blockIdx.y * 128;
    const int tid  = threadIdx.x;
    const int lane = tid & 31;
    const int w    = tid >> 5;
    const int wm   = w >> 1;
    const int wn   = w & 1;
    const int lq   = lane >> 2;
    const int lr   = lane & 3;

    if (tid < 66) {
        int t = t0 - 1 + tid;
        msk[tid] = (t >= 0 && t < T_) ? xm[b * T_ + t] : 0.f;
    }
    float acc[2][4][4];
#pragma unroll
    for (int i = 0; i < 2; i++)
#pragma unroll
        for (int j = 0; j < 4; j++)
#pragma unroll
            for (int r = 0; r < 4; r++) acc[i][j][r] = 0.f;

    const float* Xb = X + (size_t)b * C * T_;
    __syncthreads();

    for (int c0 = 0; c0 < C; c0 += 16) {
#pragma unroll
        for (int it = 0; it < 24; it++) {
            int idx = tid + it * 256;
            int ck = idx % 48, o = idx / 48;
            Ws[o * CW_S + ck] = W[(size_t)(m0 + o) * C * 3 + (size_t)c0 * 3 + ck];
        }
#pragma unroll
        for (int it = 0; it < 12; it++) {
            int idx = tid + it * 256;
            int t = idx & 63, ck = idx >> 6;
            int c = ck / 3, kk = ck % 3;
            int tg = t0 + t + kk - 1;
            float v = 0.f;
            if (tg >= 0 && tg < T_) v = Xb[(size_t)(c0 + c) * T_ + tg] * msk[t + kk];
            Xs[ck * CX_S + t] = v;
        }
        __syncthreads();
#pragma unroll
        for (int ks = 0; ks < 6; ks++) {
            const int kb = ks * 8;
            uint32_t ahi[2][4], alo[2][4];
#pragma unroll
            for (int i = 0; i < 2; i++) {
                int row = wm * 32 + i * 16 + lq;
                int col = kb + lr;
                split_tf32(Ws[row * CW_S + col],           ahi[i][0], alo[i][0]);
                split_tf32(Ws[(row + 8) * CW_S + col],     ahi[i][1], alo[i][1]);
                split_tf32(Ws[row * CW_S + col + 4],       ahi[i][2], alo[i][2]);
                split_tf32(Ws[(row + 8) * CW_S + col + 4], ahi[i][3], alo[i][3]);
            }
#pragma unroll
            for (int j = 0; j < 4; j++) {
                int tt = wn * 32 + j * 8 + lq;
                uint32_t bhi[2], blo[2];
                split_tf32(Xs[(kb + lr) * CX_S + tt],     bhi[0], blo[0]);
                split_tf32(Xs[(kb + 4 + lr) * CX_S + tt], bhi[1], blo[1]);
#pragma unroll
                for (int i = 0; i < 2; i++) {
                    mma_tf32(acc[i][j], ahi[i], bhi);
                    mma_tf32(acc[i][j], alo[i], bhi);
                    mma_tf32(acc[i][j], ahi[i], blo);
                }
            }
        }
        __syncthreads();
    }
#pragma unroll
    for (int i = 0; i < 2; i++) {
        int r0 = m0 + wm * 32 + i * 16 + lq;
        float bb0 = bias[r0], bb1 = bias[r0 + 8];
#pragma unroll
        for (int j = 0; j < 4; j++) {
            int t = t0 + wn * 32 + j * 8 + 2 * lr;
            if (t >= T_) continue;
            float v00 = acc[i][j][0] + bb0, v01 = acc[i][j][1] + bb0;
            float v10 = acc[i][j][2] + bb1, v11 = acc[i][j][3] + bb1;
            if (relu) {
                v00 = fmaxf(v00, 0.f); v01 = fmaxf(v01, 0.f);
                v10 = fmaxf(v10, 0.f); v11 = fmaxf(v11, 0.f);
            }
            if (maskout) {
                float mk0 = msk[1 + wn * 32 + j * 8 + 2 * lr];
                float mk1 = msk[1 + wn * 32 + j * 8 + 2 * lr + 1];
                v00 *= mk0; v01 *= mk1; v10 *= mk0; v11 *= mk1;
            }
            *(float2*)&Y[(size_t)b * M * T_ + (size_t)r0 * T_ + t] = make_float2(v00, v01);
            *(float2*)&Y[(size_t)b * M * T_ + (size_t)(r0 + 8) * T_ + t] = make_float2(v10, v11);
        }
    }
}

// ---------------------------------------------------------------------------
// rl[bh,t,j] = scale * sum_d Q[bh,d,t] * ek[j,d]
__global__ void relk_kernel(const float* __restrict__ ek, float scale) {
    int w = (blockIdx.x * blockDim.x + threadIdx.x) >> 5;
    int lane = threadIdx.x & 31;
    if (w >= B_ * NH_ * T_) return;
    int bh = w / T_, t = w % T_;
    const float* qb = g_q + (size_t)bh * HEAD_ * T_ + t;
    float q0 = qb[(size_t)lane * T_] * scale;
    float q1 = qb[(size_t)(lane + 32) * T_] * scale;
#pragma unroll
    for (int j = 0; j < 9; j++) {
        float v = q0 * ek[j * HEAD_ + lane] + q1 * ek[j * HEAD_ + lane + 32];
#pragma unroll
        for (int off = 16; off > 0; off >>= 1) v += __shfl_down_sync(0xffffffffu, v, off);
        if (lane == 0) g_rl[w * 9 + j] = v;
    }
}

// ---------------------------------------------------------------------------
// Scores on tensor cores. Tile 128(t) x 64(s), BK=32 over HEAD=64.
// Epilogue fuses scale, banded rel bias, and mask (-> softmax is pure).
#define QS_S 136
#define KS_S 72
__global__ __launch_bounds__(256, 2) void scores_tc_kernel(
    const float* __restrict__ xm, float scale)
{
    __shared__ float Qs[32 * QS_S];
    __shared__ float Ks[32 * KS_S];
    const int bh = blockIdx.z;
    const int b  = bh >> 3;               // NH_ = 8
    const int s0 = blockIdx.x * 64;
    const int t0 = blockIdx.y * 128;
    const float* Qb = g_q + (size_t)bh * HEAD_ * T_;
    const float* Kb = g_k + (size_t)bh * HEAD_ * T_;
    float* Sb = g_p + (size_t)bh * T_ * T_;
    const int tid  = threadIdx.x;
    const int lane = tid & 31;
    const int w    = tid >> 5;
    const int wm   = w >> 1;
    const int wn   = w & 1;
    const int lq   = lane >> 2;
    const int lr   = lane & 3;

    float acc[2][4][4];
#pragma unroll
    for (int i = 0; i < 2; i++)
#pragma unroll
        for (int j = 0; j < 4; j++)
#pragma unroll
            for (int r = 0; r < 4; r++) acc[i][j][r] = 0.f;

    for (int k0 = 0; k0 < HEAD_; k0 += 32) {
#pragma unroll
        for (int it = 0; it < 16; it++) {
            int idx = tid + it * 256;
            int t = idx & 127, kk = idx >> 7;
            int tg = t0 + t;
            Qs[kk * QS_S + t] = (tg < T_) ? Qb[(size_t)(k0 + kk) * T_ + tg] : 0.f;
        }
#pragma unroll
        for (int it = 0; it < 8; it++) {
            int idx = tid + it * 256;
            int s = idx & 63, kk = idx >> 6;
            int sg = s0 + s;
            Ks[kk * KS_S + s] = (sg < T_) ? Kb[(size_t)(k0 + kk) * T_ + sg] : 0.f;
        }
        __syncthreads();
#pragma unroll
        for (int ks = 0; ks < 4; ks++) {
            const int kb = ks * 8;
            uint32_t ahi[2][4], alo[2][4];
#pragma unroll
            for (int i = 0; i < 2; i++) {
                int row = wm * 32 + i * 16 + lq;     // t within tile
                split_tf32(Qs[(kb + lr) * QS_S + row],         ahi[i][0], alo[i][0]);
                split_tf32(Qs[(kb + lr) * QS_S + row + 8],     ahi[i][1], alo[i][1]);
                split_tf32(Qs[(kb + 4 + lr) * QS_S + row],     ahi[i][2], alo[i][2]);
                split_tf32(Qs[(kb + 4 + lr) * QS_S + row + 8], ahi[i][3], alo[i][3]);
            }
#pragma unroll
            for (int j = 0; j < 4; j++) {
                int sn = wn * 32 + j * 8 + lq;
                uint32_t bhi[2], blo[2];
                split_tf32(Ks[(kb + lr) * KS_S + sn],     bhi[0], blo[0]);
                split_tf32(Ks[(kb + 4 + lr) * KS_S + sn], bhi[1], blo[1]);
#pragma unroll
                for (int i = 0; i < 2; i++) {
                    mma_tf32(acc[i][j], ahi[i], bhi);
                    mma_tf32(acc[i][j], alo[i], bhi);
                    mma_tf32(acc[i][j], ahi[i], blo);
                }
            }
        }
        __syncthreads();
    }
    // epilogue: scale + banded bias + mask
#pragma unroll
    for (int i = 0; i < 2; i++) {
        int tA = t0 + wm * 32 + i * 16 + lq;
        int tB = tA + 8;
        float mtA = (tA < T_) ? xm[b * T_ + tA] : 0.f;
        float mtB = (tB < T_) ? xm[b * T_ + tB] : 0.f;
#pragma unroll
        for (int j = 0; j < 4; j++) {
            int s = s0 + wn * 32 + j * 8 + 2 * lr;
            if (s + 1 >= T_ && s >= T_) continue;
#pragma unroll
            for (int cc = 0; cc < 2; cc++) {
                int sc = s + cc;
                if (sc >= T_) continue;
                float ms = xm[b * T_ + sc];
                if (tA < T_) {
                    float val = acc[i][j][cc] * scale;
                    int jj = sc - tA + 4;
                    if (jj >= 0 && jj < 9) val += g_rl[((size_t)bh * T_ + tA) * 9 + jj];
                    if (mtA == 0.f || ms == 0.f) val = -10000.0f;
                    Sb[(size_t)tA * T_ + sc] = val;
                }
                if (tB < T_) {
                    float val = acc[i][j][cc + 2] * scale;
                    int jj = sc - tB + 4;
                    if (jj >= 0 && jj < 9) val += g_rl[((size_t)bh * T_ + tB) * 9 + jj];
                    if (mtB == 0.f || ms == 0.f) val = -10000.0f;
                    Sb[(size_t)tB * T_ + sc] = val;
                }
            }
        }
    }
}

// ---------------------------------------------------------------------------
// Pure row softmax (bias/mask already in scores).
__global__ __launch_bounds__(256) void softmax_kernel() {
    const int row = blockIdx.x;
    const int bh = row / T_, t = row % T_;
    float* P = g_p + (size_t)bh * T_ * T_ + (size_t)t * T_;
    const int tid = threadIdx.x;
    float v[4];
#pragma unroll
    for (int r = 0; r < 4; r++) {
        int s = tid + r * 256;
        v[r] = (s < T_) ? P[s] : -1e30f;
    }
    __shared__ float red[256];
    float mx = fmaxf(fmaxf(v[0], v[1]), fmaxf(v[2], v[3]));
    red[tid] = mx;
    __syncthreads();
    for (int off = 128; off > 0; off >>= 1) {
        if (tid < off) red[tid] = fmaxf(red[tid], red[tid + off]);
        __syncthreads();
    }
    mx = red[0];
    __syncthreads();
    float sum = 0.f;
#pragma unroll
    for (int r = 0; r < 4; r++) {
        v[r] = __expf(v[r] - mx);
        if (tid + r * 256 < T_) sum += v[r];
    }
    red[tid] = sum;
    __syncthreads();
    for (int off = 128; off > 0; off >>= 1) {
        if (tid < off) red[tid] += red[tid + off];
        __syncthreads();
    }
    float inv = 1.f / red[0];
#pragma unroll
    for (int r = 0; r < 4; r++) {
        int s = tid + r * 256;
        if (s < T_) P[s] = v[r] * inv;
    }
}

// ---------------------------------------------------------------------------
// AV on tensor cores: O[d,t] = sum_s V[d,s] P[t,s]. Tile 64(d) x 128(t), BK=32.
#define VS_S 36
#define PS_S 36
__global__ __launch_bounds__(256, 2) void av_tc_kernel() {
    __shared__ float Vs[64 * VS_S];
    __shared__ float Ps[128 * PS_S];
    const int bh = blockIdx.y;
    const int t0 = blockIdx.x * 128;
    const float* Vb = g_v + (size_t)bh * HEAD_ * T_;
    const float* Pb = g_p + (size_t)bh * T_ * T_;
    float* Ob = g_att + (size_t)bh * HEAD_ * T_;
    const int tid  = threadIdx.x;
    const int lane = tid & 31;
    const int w    = tid >> 5;
    const int wm   = w >> 2;          // 0..1 (d)
    const int wn   = w & 3;           // 0..3 (t)
    const int lq   = lane >> 2;
    const int lr   = lane & 3;

    float acc[2][4][4];
#pragma unroll
    for (int i = 0; i < 2; i++)
#pragma unroll
        for (int j = 0; j < 4; j++)
#pragma unroll
            for (int r = 0; r < 4; r++) acc[i][j][r] = 0.f;

    for (int k0 = 0; k0 < T_; k0 += 32) {
#pragma unroll
        for (int it = 0; it < 8; it++) {
            int idx = tid + it * 256;
            int s = idx & 31, d = idx >> 5;
            Vs[d * VS_S + s] = Vb[(size_t)d * T_ + k0 + s];
        }
#pragma unroll
        for (int it = 0; it < 16; it++) {
            int idx = tid + it * 256;
            int s = idx & 31, t = idx >> 5;
            int tg = t0 + t;
            Ps[t * PS_S + s] = (tg < T_) ? Pb[(size_t)tg * T_ + k0 + s] : 0.f;
        }
        __syncthreads();
#pragma unroll
        for (int ks = 0; ks < 4; ks++) {
            const int kb = ks * 8;
            uint32_t ahi[2][4], alo[2][4];
#pragma unroll
            for (int i = 0; i < 2; i++) {
                int row = wm * 32 + i * 16 + lq;     // d
                split_tf32(Vs[row * VS_S + kb + lr],           ahi[i][0], alo[i][0]);
                split_tf32(Vs[(row + 8) * VS_S + kb + lr],     ahi[i][1], alo[i][1]);
                split_tf32(Vs[row * VS_S + kb + 4 + lr],       ahi[i][2], alo[i][2]);
                split_tf32(Vs[(row + 8) * VS_S + kb + 4 + lr], ahi[i][3], alo[i][3]);
            }
#pragma unroll
            for (int j = 0; j < 4; j++) {
                int tn = wn * 32 + j * 8 + lq;
                uint32_t bhi[2], blo[2];
                split_tf32(Ps[tn * PS_S + kb + lr],     bhi[0], blo[0]);
                split_tf32(Ps[tn * PS_S + kb + 4 + lr], bhi[1], blo[1]);
#pragma unroll
                for (int i = 0; i < 2; i++) {
                    mma_tf32(acc[i][j], ahi[i], bhi);
                    mma_tf32(acc[i][j], alo[i], bhi);
                    mma_tf32(acc[i][j], ahi[i], blo);
                }
            }
        }
        __syncthreads();
    }
#pragma unroll
    for (int i = 0; i < 2; i++) {
        int d0 = wm * 32 + i * 16 + lq;
#pragma unroll
        for (int j = 0; j < 4; j++) {
            int t = t0 + wn * 32 + j * 8 + 2 * lr;
            if (t >= T_) continue;
            *(float2*)&Ob[(size_t)d0 * T_ + t] = make_float2(acc[i][j][0], acc[i][j][1]);
            *(float2*)&Ob[(size_t)(d0 + 8) * T_ + t] = make_float2(acc[i][j][2], acc[i][j][3]);
        }
    }
}

// ---------------------------------------------------------------------------
// O[bh,d,t] += sum_{j=0..8} P[bh,t,t+j-4] * ev[j,d]
__global__ __launch_bounds__(256) void addrelv_kernel(const float* __restrict__ ev) {
    __shared__ float pband[32][9];
    __shared__ float evs[9 * 64];
    const int bh = blockIdx.y;
    const int t0 = blockIdx.x * 32;
    const float* Pb = g_p + (size_t)bh * T_ * T_;
    float* Ob = g_att + (size_t)bh * HEAD_ * T_;
    const int tid = threadIdx.x;
    for (int idx = tid; idx < 9 * 64; idx += 256) evs[idx] = ev[idx];
    for (int idx = tid; idx < 32 * 9; idx += 256) {
        int tl = idx / 9, j = idx % 9;
        int t = t0 + tl, s = t + j - 4;
        pband[tl][j] = (t < T_ && s >= 0 && s < T_) ? Pb[(size_t)t * T_ + s] : 0.f;
    }
    __syncthreads();
    int tl = tid & 31, dg = tid >> 5;
    int t = t0 + tl;
    if (t >= T_) return;
#pragma unroll
    for (int dd = 0; dd < 8; dd++) {
        int d = dg * 8 + dd;
        float sum = 0.f;
#pragma unroll
        for (int j = 0; j < 9; j++) sum += pband[tl][j] * evs[j * 64 + d];
        Ob[(size_t)d * T_ + t] += sum;
    }
}

// ---------------------------------------------------------------------------
__global__ void ln_kernel(const float* __restrict__ Yadd, const float* __restrict__ g,
                          const float* __restrict__ be) {
    const int b = blockIdx.y;
    const int tx = threadIdx.x;
    const int ty = threadIdx.y;
    const int t = blockIdx.x * 32 + tx;
    __shared__ float r1[8][32], r2[8][32];
    __shared__ float mu[32], wv[32];
    float s1 = 0.f, s2 = 0.f;
    if (t < T_) {
        for (int c = ty; c < H_; c += 8) {
            size_t off = (size_t)b * H_ * T_ + (size_t)c * T_ + t;
            float v = g_h[off] + Yadd[off];
            s1 += v; s2 += v * v;
        }
    }
    r1[ty][tx] = s1; r2[ty][tx] = s2;
    __syncthreads();
    if (ty == 0) {
        float a1 = 0.f, a2 = 0.f;
#pragma unroll
        for (int i = 0; i < 8; i++) { a1 += r1[i][tx]; a2 += r2[i][tx]; }
        float m = a1 / H_;
        float var = a2 / H_ - m * m;
        mu[tx] = m;
        wv[tx] = rsqrtf(var + 1e-5f);
    }
    __syncthreads();
    if (t < T_) {
        float m = mu[tx], ww = wv[tx];
        for (int c = ty; c < H_; c += 8) {
            size_t off = (size_t)b * H_ * T_ + (size_t)c * T_ + t;
            float v = g_h[off] + Yadd[off];
            g_h[off] = (v - m) * ww * g[c] + be[c];
        }
    }
}

// ---------------------------------------------------------------------------
__global__ void finalize_kernel(const float* __restrict__ prior, const float* __restrict__ xm,
                                float* __restrict__ out) {
    int idx = blockIdx.x * blockDim.x + threadIdx.x;
    const int total = B_ * 2 * H_ * T_;
    if (idx >= total) return;
    int t = idx % T_;
    int o = (idx / T_) % (2 * H_);
    int b = idx / (2 * H_ * T_);
    float v = prior[idx] * xm[b * T_ + t];
    size_t dst = (size_t)(o < H_ ? 0 : BHT_) + (size_t)b * H_ * T_ + (size_t)(o & (H_ - 1)) * T_ + t;
    out[dst] = v;
}

// ---------------------------------------------------------------------------
extern "C" void kernel_launch(void* const* d_in, const int* in_sizes, int n_in,
                              void* d_out, int out_size) {
    const float* x   = (const float*)d_in[0];
    const float* xm  = (const float*)d_in[1];
    const float* Wq  = (const float*)d_in[2];
    const float* bq  = (const float*)d_in[3];
    const float* Wk  = (const float*)d_in[4];
    const float* bk  = (const float*)d_in[5];
    const float* Wv  = (const float*)d_in[6];
    const float* bv  = (const float*)d_in[7];
    const float* Wo  = (const float*)d_in[8];
    const float* bo  = (const float*)d_in[9];
    const float* ek  = (const float*)d_in[10];
    const float* ev  = (const float*)d_in[11];
    const float* g1  = (const float*)d_in[12];
    const float* b1  = (const float*)d_in[13];
    const float* g2  = (const float*)d_in[14];
    const float* b2  = (const float*)d_in[15];
    const float* Wf1 = (const float*)d_in[16];
    const float* bf1 = (const float*)d_in[17];
    const float* Wf2 = (const float*)d_in[18];
    const float* bf2 = (const float*)d_in[19];
    const float* Wp  = (const float*)d_in[20];
    const float* bp  = (const float*)d_in[21];
    float* out = (float*)d_out;

    float *ph, *pq, *pk, *pv, *patt, *py, *pff;
    cudaGetSymbolAddress((void**)&ph,  g_h);
    cudaGetSymbolAddress((void**)&pq,  g_q);
    cudaGetSymbolAddress((void**)&pk,  g_k);
    cudaGetSymbolAddress((void**)&pv,  g_v);
    cudaGetSymbolAddress((void**)&patt, g_att);
    cudaGetSymbolAddress((void**)&py,  g_y);
    cudaGetSymbolAddress((void**)&pff, g_ff);

    const float scale = 0.125f;
    const int TT = (T_ + 63) / 64;       // 13
    const int TT128 = (T_ + 127) / 128;  // 7
    const int TB32 = (T_ + 31) / 32;     // 25

    init_h_kernel<<<(BHT_ + 255) / 256, 256>>>(x, xm);

    for (int L = 0; L < NL_; L++) {
        const float* wq  = Wq  + (size_t)L * H_ * H_;
        const float* wk  = Wk  + (size_t)L * H_ * H_;
        const float* wv  = Wv  + (size_t)L * H_ * H_;
        const float* wo  = Wo  + (size_t)L * H_ * H_;
        const float* ekL = ek  + (size_t)L * 9 * HEAD_;
        const float* evL = ev  + (size_t)L * 9 * HEAD_;
        const float* wf1 = Wf1 + (size_t)L * FF_ * H_ * 3;
        const float* wf2 = Wf2 + (size_t)L * H_ * FF_ * 3;

        gemm3_tc_kernel<<<dim3(TT, 12, B_), 256>>>(wq, bq + L * H_, pq,
                                                   wk, bk + L * H_, pk,
                                                   wv, bv + L * H_, pv, ph);

        relk_kernel<<<(B_ * NH_ * T_ * 32 + 127) / 128, 128>>>(ekL, scale);
        scores_tc_kernel<<<dim3(TT, TT128, B_ * NH_), 256>>>(xm, scale);
        softmax_kernel<<<B_ * NH_ * T_, 256>>>();
        av_tc_kernel<<<dim3(TT128, B_ * NH_), 256>>>();
        addrelv_kernel<<<dim3(TB32, B_ * NH_), 256>>>(evL);

        gemm_tc_kernel<<<dim3(TT, H_ / 128, B_), 256>>>(wo, bo + L * H_, patt, pq, H_, H_);
        ln_kernel<<<dim3(TB32, B_), dim3(32, 8)>>>(pq, g1 + L * H_, b1 + L * H_);

        conv_tc_kernel<<<dim3(TT, FF_ / 128, B_), 256>>>(wf1, bf1 + L * FF_, ph, pff, xm, FF_, H_, 1, 0);
        conv_tc_kernel<<<dim3(TT, H_ / 128, B_), 256>>>(wf2, bf2 + L * H_, pff, py, xm, H_, FF_, 0, 1);
        ln_kernel<<<dim3(TB32, B_), dim3(32, 8)>>>(py, g2 + L * H_, b2 + L * H_);
    }

    maskh_kernel<<<(BHT_ + 255) / 256, 256>>>(xm);
    gemm_tc_kernel<<<dim3(TT, 2 * H_ / 128, B_), 256>>>(Wp, bp, ph, pff, 2 * H_, H_);
    finalize_kernel<<<(B_ * 2 * H_ * T_ + 255) / 256, 256>>>(pff, xm, out);
}